// round 16
// baseline (speedup 1.0000x reference)
#include <cuda_runtime.h>
#include <cstdint>

// ---------------- problem constants ----------------
#define MAX_E 120000
#define MAX_N 5000

typedef unsigned long long u64;

// ---------------- scratch (static __device__, allocation-free) ----------------
__device__ float g_cut[MAX_E];
__device__ float g_lat[MAX_E * 128];
__device__ float g_fs[MAX_E * 16];
__device__ float g_fv[MAX_E * 48];
__device__ float g_scal[MAX_E * 32];
__device__ float g_V[MAX_E * 144];
__device__ float g_env_s[MAX_N * 16];
__device__ float g_env_v[MAX_N * 48];
__device__ float g_env_s2[MAX_N * 16];
__device__ float g_env_v2[MAX_N * 48];
__device__ float g_w1f[2 * 20480];         // l2w W1 frag-packed, both layers
__device__ float g_w2f[2 * 163840];        // l2w W2 frag-packed, both layers
__device__ float g_mw1f[16 * 20 * 128];    // MLP W1 frag-packed hi/lo
__device__ float g_mw2f[16 * 16 * 128];    // MLP W2 frag-packed hi/lo

// ---------------- math constants ----------------
constexpr float C_OLD    = 0.8944271909999159f;
constexpr float A_C_OLD  = 0.4472135954999579f;
constexpr float INV_S3   = 0.5773502691896258f;
constexpr float INV_S2   = 0.7071067811865476f;
constexpr float C_FS     = 0.17677669529663687f;
constexpr float C_FV     = 0.14433756729740643f;
constexpr float NORM_LIN = 0.05590169943749474f;
constexpr float INV_SM   = 0.25f;

__device__ __forceinline__ float silu_f(float x) { return x / (1.f + __expf(-x)); }

// ---------------- tf32 helpers ----------------
__device__ __forceinline__ float tf32r(float x) {
    uint32_t u;
    asm("cvt.rna.tf32.f32 %0, %1;" : "=r"(u) : "f"(x));
    return __uint_as_float(u);
}
__device__ __forceinline__ void mma_tf32(float& d0, float& d1, float& d2, float& d3,
                                         uint32_t a0, uint32_t a1, uint32_t a2, uint32_t a3,
                                         uint32_t b0, uint32_t b1) {
    asm volatile(
        "mma.sync.aligned.m16n8k8.row.col.f32.tf32.tf32.f32 "
        "{%0,%1,%2,%3}, {%4,%5,%6,%7}, {%8,%9}, {%0,%1,%2,%3};"
        : "+f"(d0), "+f"(d1), "+f"(d2), "+f"(d3)
        : "r"(a0), "r"(a1), "r"(a2), "r"(a3), "r"(b0), "r"(b1));
}
__device__ __forceinline__ uint32_t fbits(float x) { return __float_as_uint(x); }

// ---------------- per-node / per-edge helper kernels ----------------
__global__ void k_envlin(const float* __restrict__ Ws, const float* __restrict__ Wv, int N) {
    const int idx = blockIdx.x * blockDim.x + threadIdx.x;
    if (idx >= N * 16) return;
    const int n = idx >> 4, v = idx & 15;
    float s = 0.f, v0 = 0.f, v1 = 0.f, v2 = 0.f;
#pragma unroll
    for (int u = 0; u < 16; u++) {
        const float wsv = Ws[u * 16 + v];
        const float wvv = Wv[u * 16 + v];
        s  = fmaf(g_env_s[n * 16 + u], wsv, s);
        v0 = fmaf(g_env_v[n * 48 + u * 3 + 0], wvv, v0);
        v1 = fmaf(g_env_v[n * 48 + u * 3 + 1], wvv, v1);
        v2 = fmaf(g_env_v[n * 48 + u * 3 + 2], wvv, v2);
    }
    g_env_s2[n * 16 + v] = s * NORM_LIN;
    g_env_v2[n * 48 + v * 3 + 0] = v0 * NORM_LIN;
    g_env_v2[n * 48 + v * 3 + 1] = v1 * NORM_LIN;
    g_env_v2[n * 48 + v * 3 + 2] = v2 * NORM_LIN;
}

// zero_env: also clear env accumulators for the NEXT layer (this layer's envlin
// already consumed them earlier in stream order).
__global__ void k_combine(const int* __restrict__ edge_index, int E, int zero_env) {
    const int idx = blockIdx.x * blockDim.x + threadIdx.x;
    if (zero_env) {
        if (idx < MAX_N * 16) g_env_s[idx] = 0.f;
        else if (idx < MAX_N * 64) g_env_v[idx - MAX_N * 16] = 0.f;
    }
    if (idx >= E * 16) return;
    const int e = idx >> 4, u = idx & 15;
    const int c = edge_index[e];
    const float es  = g_env_s2[c * 16 + u];
    const float ev0 = g_env_v2[c * 48 + u * 3 + 0];
    const float ev1 = g_env_v2[c * 48 + u * 3 + 1];
    const float ev2 = g_env_v2[c * 48 + u * 3 + 2];
    const float fsv = g_fs[e * 16 + u];
    const float fv0 = g_fv[e * 48 + u * 3 + 0];
    const float fv1 = g_fv[e * 48 + u * 3 + 1];
    const float fv2 = g_fv[e * 48 + u * 3 + 2];

    g_scal[e * 32 + 2 * u]     = fsv * es;
    g_scal[e * 32 + 2 * u + 1] = (fv0 * ev0 + fv1 * ev1 + fv2 * ev2) * INV_S3;

    float* Vp = &g_V[e * 144];
    Vp[u * 3 + 0] = fsv * ev0;
    Vp[u * 3 + 1] = fsv * ev1;
    Vp[u * 3 + 2] = fsv * ev2;
    Vp[48 + u * 3 + 0] = fv0 * es;
    Vp[48 + u * 3 + 1] = fv1 * es;
    Vp[48 + u * 3 + 2] = fv2 * es;
    Vp[96 + u * 3 + 0] = (fv1 * ev2 - fv2 * ev1) * INV_S2;
    Vp[96 + u * 3 + 1] = (fv2 * ev0 - fv0 * ev2) * INV_S2;
    Vp[96 + u * 3 + 2] = (fv0 * ev1 - fv1 * ev0) * INV_S2;
}

// ---------------- l2w weight frag-packing (plain tf32, per-layer dst) --------------
__global__ void k_pack_w1(const float* __restrict__ W1, float* __restrict__ dst) {
    const int idx = blockIdx.x * blockDim.x + threadIdx.x;
    if (idx >= 16 * 20 * 64) return;
    const int frag = idx >> 6;
    const int r = idx & 63;
    const int lane = r >> 1, z = r & 1;
    const int ch = frag / 20, ks = frag % 20;
    const int n = ch * 8 + (lane >> 2);
    const int k = ks * 8 + (lane & 3) + z * 4;
    dst[idx] = tf32r(W1[k * 128 + n]);
}
__global__ void k_pack_w2(const float* __restrict__ W2, float* __restrict__ dst) {
    const int idx = blockIdx.x * blockDim.x + threadIdx.x;
    if (idx >= 80 * 2 * 16 * 64) return;
    const int frag = idx >> 6;
    const int r = idx & 63;
    const int lane = r >> 1, z = r & 1;
    const int puh = frag >> 4, ks = frag & 15;
    const int pu = puh >> 1, h = puh & 1;
    const int n = pu * 16 + h * 8 + (lane >> 2);
    const int k = ks * 8 + (lane & 3) + z * 4;
    dst[idx] = tf32r(W2[k * 1280 + n]);
}

// ---------------- MLP weight frag-packing (hi/lo for 3xTF32) ----------------
// zero_env: extra thread range clears env accumulators (fused memset).
__global__ void k_pack_mlp(const float* __restrict__ W1, int KS1,
                           const float* __restrict__ W2, int NCH2, int OUT,
                           int zero_env) {
    const int tid = blockIdx.x * blockDim.x + threadIdx.x;
    const int n1 = 16 * KS1;
    const int packTotal = (n1 + NCH2 * 16) * 32;
    if (tid >= packTotal) {
        if (zero_env) {
            const int z = tid - packTotal;
            if (z < MAX_N * 16) g_env_s[z] = 0.f;
            else if (z < MAX_N * 64) g_env_v[z - MAX_N * 16] = 0.f;
        }
        return;
    }
    const int frag = tid >> 5, lane = tid & 31;
    const float* W;
    float* dst;
    int ldn, fl, ch, ks;
    if (frag < n1) {
        W = W1; ldn = 128; dst = g_mw1f; fl = frag;
        ch = fl / KS1; ks = fl - ch * KS1;
    } else {
        W = W2; ldn = OUT; dst = g_mw2f; fl = frag - n1;
        ch = fl >> 4; ks = fl & 15;
    }
    const int n = ch * 8 + (lane >> 2);
    const int k = ks * 8 + (lane & 3);
    const float w0 = W[k * ldn + n];
    const float w1 = W[(k + 4) * ldn + n];
    const float h0 = tf32r(w0), h1 = tf32r(w1);
    float4 o;
    o.x = h0; o.y = h1;
    o.z = tf32r(w0 - h0); o.w = tf32r(w1 - h1);
    *reinterpret_cast<float4*>(&dst[fl * 128 + lane * 4]) = o;
}

// ---------------- tensor-core MLP: Y = silu(X@W1)@W2, 3xTF32 ----------
// STAGE: 0 = X=g_lat(128); 1 = X=[g_lat|g_scal](160); 2 = gather x2b(16) + cut.
// EPI:   0 = store Y;  1 = lat blend;  2 = cut-scale into g_lat;
//        3 = env0 fused; 4 = env1 fused; 5 = final fused output contraction.
template <int IN, int KS1, int NCH2, int STAGE, int EPI>
__global__ void __launch_bounds__(256, 2)
k_mlp_tc(const float* __restrict__ Xa, const float* __restrict__ Xb,
         const float* __restrict__ edge_u, const int* __restrict__ edge_index,
         const float* __restrict__ edge_attr,
         float* __restrict__ Y, int E) {
    constexpr int XSTR = (IN >= 128) ? IN + 5 : 133;
    constexpr int OUT = NCH2 * 8;
    extern __shared__ float sm[];
    float* Xs = sm;
    const int t = threadIdx.x, lane = t & 31, w = t >> 5;
    const int g = lane >> 2, q = lane & 3;
    const int e0 = blockIdx.x * 128;
    const bool full = (e0 + 128 <= E);

    if (STAGE == 2) {
        for (int idx = t; idx < 128 * 16; idx += 256) {
            const int le = idx >> 4, c = idx & 15;
            const int e = e0 + le;
            float v = 0.f;
            if (e < E) {
                if (c < 4)       v = Xa[edge_index[e] * 4 + c];
                else if (c < 8)  v = Xa[edge_index[E + e] * 4 + (c - 4)];
                else             v = Xb[e * 8 + (c - 8)];
            }
            Xs[le * XSTR + c] = v;
        }
        if (t < 128) {
            const int e = e0 + t;
            if (e < E) {
                const float u = edge_u[e];
                const float u2 = u * u, u3 = u2 * u, u6 = u3 * u3;
                const float f = 1.f - 28.f * u6 + 48.f * u6 * u - 21.f * u6 * u2;
                g_cut[e] = (u < 1.f) ? f : 0.f;
            }
        }
    } else if (full) {
        constexpr int C4 = IN / 4;
        for (int idx = t; idx < 128 * C4; idx += 256) {
            const int le = idx / C4, c4 = idx - le * C4;
            const int e = e0 + le;
            const int c = c4 * 4;
            float4 v;
            if (STAGE == 0 || c < 128) v = *reinterpret_cast<const float4*>(&Xa[e * 128 + c]);
            else                       v = *reinterpret_cast<const float4*>(&Xb[e * 32 + (c - 128)]);
            float* p = &Xs[le * XSTR + c];
            p[0] = v.x; p[1] = v.y; p[2] = v.z; p[3] = v.w;
        }
    } else {
        for (int idx = t; idx < 128 * IN; idx += 256) {
            const int le = idx / IN, c = idx - le * IN;
            const int e = e0 + le;
            float v = 0.f;
            if (e < E) v = (STAGE == 0 || c < 128) ? Xa[e * 128 + c] : Xb[e * 32 + (c - 128)];
            Xs[le * XSTR + c] = v;
        }
    }
    __syncthreads();

    const int r0 = w * 16 + g;

    // ---- GEMM1 ----
    {
        float acc[16][4];
#pragma unroll
        for (int c = 0; c < 16; c++)
#pragma unroll
            for (int j = 0; j < 4; j++) acc[c][j] = 0.f;

#pragma unroll 1
        for (int ks = 0; ks < KS1; ks++) {
            const int k0 = ks * 8;
            const float x0 = Xs[r0 * XSTR + k0 + q];
            const float x1 = Xs[(r0 + 8) * XSTR + k0 + q];
            const float x2 = Xs[r0 * XSTR + k0 + q + 4];
            const float x3 = Xs[(r0 + 8) * XSTR + k0 + q + 4];
            const float h0 = tf32r(x0), h1 = tf32r(x1), h2 = tf32r(x2), h3 = tf32r(x3);
            const uint32_t ah0 = fbits(h0), ah1 = fbits(h1), ah2 = fbits(h2), ah3 = fbits(h3);
            const uint32_t al0 = fbits(tf32r(x0 - h0)), al1 = fbits(tf32r(x1 - h1));
            const uint32_t al2 = fbits(tf32r(x2 - h2)), al3 = fbits(tf32r(x3 - h3));
#pragma unroll
            for (int ch = 0; ch < 16; ch++) {
                const float4 b = *reinterpret_cast<const float4*>(
                    &g_mw1f[(ch * KS1 + ks) * 128 + lane * 4]);
                const uint32_t bh0 = fbits(b.x), bh1 = fbits(b.y);
                const uint32_t bl0 = fbits(b.z), bl1 = fbits(b.w);
                mma_tf32(acc[ch][0], acc[ch][1], acc[ch][2], acc[ch][3],
                         al0, al1, al2, al3, bh0, bh1);
                mma_tf32(acc[ch][0], acc[ch][1], acc[ch][2], acc[ch][3],
                         ah0, ah1, ah2, ah3, bl0, bl1);
                mma_tf32(acc[ch][0], acc[ch][1], acc[ch][2], acc[ch][3],
                         ah0, ah1, ah2, ah3, bh0, bh1);
            }
        }
        __syncwarp();
#pragma unroll
        for (int ch = 0; ch < 16; ch++) {
            const int col = ch * 8 + 2 * q;
            Xs[r0 * XSTR + col]           = silu_f(acc[ch][0]);
            Xs[r0 * XSTR + col + 1]       = silu_f(acc[ch][1]);
            Xs[(r0 + 8) * XSTR + col]     = silu_f(acc[ch][2]);
            Xs[(r0 + 8) * XSTR + col + 1] = silu_f(acc[ch][3]);
        }
        __syncwarp();
    }

    // ---- GEMM2: ks outer / ch inner ----
    float acc2[NCH2][4];
#pragma unroll
    for (int c = 0; c < NCH2; c++)
#pragma unroll
        for (int j = 0; j < 4; j++) acc2[c][j] = 0.f;

#pragma unroll 1
    for (int ks = 0; ks < 16; ks++) {
        const int k0 = ks * 8;
        const float x0 = Xs[r0 * XSTR + k0 + q];
        const float x1 = Xs[(r0 + 8) * XSTR + k0 + q];
        const float x2 = Xs[r0 * XSTR + k0 + q + 4];
        const float x3 = Xs[(r0 + 8) * XSTR + k0 + q + 4];
        const float h0 = tf32r(x0), h1 = tf32r(x1), h2 = tf32r(x2), h3 = tf32r(x3);
        const uint32_t ah0 = fbits(h0), ah1 = fbits(h1), ah2 = fbits(h2), ah3 = fbits(h3);
        const uint32_t al0 = fbits(tf32r(x0 - h0)), al1 = fbits(tf32r(x1 - h1));
        const uint32_t al2 = fbits(tf32r(x2 - h2)), al3 = fbits(tf32r(x3 - h3));
#pragma unroll
        for (int ch = 0; ch < NCH2; ch++) {
            const float4 b = *reinterpret_cast<const float4*>(
                &g_mw2f[(ch * 16 + ks) * 128 + lane * 4]);
            const uint32_t bh0 = fbits(b.x), bh1 = fbits(b.y);
            const uint32_t bl0 = fbits(b.z), bl1 = fbits(b.w);
            mma_tf32(acc2[ch][0], acc2[ch][1], acc2[ch][2], acc2[ch][3],
                     al0, al1, al2, al3, bh0, bh1);
            mma_tf32(acc2[ch][0], acc2[ch][1], acc2[ch][2], acc2[ch][3],
                     ah0, ah1, ah2, ah3, bl0, bl1);
            mma_tf32(acc2[ch][0], acc2[ch][1], acc2[ch][2], acc2[ch][3],
                     ah0, ah1, ah2, ah3, bh0, bh1);
        }
    }

    // ---- epilogue ----
    const int er0 = e0 + r0, er8 = er0 + 8;
    float cut0 = 0.f, cut8 = 0.f;
    if (EPI == 1 || EPI == 2) {
        cut0 = (er0 < E) ? g_cut[er0] : 0.f;
        cut8 = (er8 < E) ? g_cut[er8] : 0.f;
    }
    float ea0[4] = {0.f, 0.f, 0.f, 0.f}, ea8[4] = {0.f, 0.f, 0.f, 0.f};
    int c0 = 0, c8 = 0;
    if (EPI == 3 || EPI == 4) {
        if (er0 < E) {
            const float4 a = *reinterpret_cast<const float4*>(&edge_attr[er0 * 4]);
            ea0[0] = a.x; ea0[1] = a.y; ea0[2] = a.z; ea0[3] = a.w;
            c0 = edge_index[er0];
        }
        if (er8 < E) {
            const float4 a = *reinterpret_cast<const float4*>(&edge_attr[er8 * 4]);
            ea8[0] = a.x; ea8[1] = a.y; ea8[2] = a.z; ea8[3] = a.w;
            c8 = edge_index[er8];
        }
    }
    float o0[3] = {0.f, 0.f, 0.f}, o8[3] = {0.f, 0.f, 0.f};

#pragma unroll
    for (int ch = 0; ch < NCH2; ch++) {
        const int n0 = ch * 8 + 2 * q;
        const float d0 = acc2[ch][0], d1 = acc2[ch][1];
        const float d2 = acc2[ch][2], d3 = acc2[ch][3];
        if (EPI == 0) {
            if (er0 < E) { Y[er0 * OUT + n0] = d0; Y[er0 * OUT + n0 + 1] = d1; }
            if (er8 < E) { Y[er8 * OUT + n0] = d2; Y[er8 * OUT + n0 + 1] = d3; }
        } else if (EPI == 1) {
            if (er0 < E) {
                float* p = &g_lat[er0 * 128 + n0];
                p[0] = C_OLD * p[0] + A_C_OLD * cut0 * d0;
                p[1] = C_OLD * p[1] + A_C_OLD * cut0 * d1;
            }
            if (er8 < E) {
                float* p = &g_lat[er8 * 128 + n0];
                p[0] = C_OLD * p[0] + A_C_OLD * cut8 * d2;
                p[1] = C_OLD * p[1] + A_C_OLD * cut8 * d3;
            }
        } else if (EPI == 2) {
            if (er0 < E) {
                g_lat[er0 * 128 + n0]     = cut0 * d0;
                g_lat[er0 * 128 + n0 + 1] = cut0 * d1;
            }
            if (er8 < E) {
                g_lat[er8 * 128 + n0]     = cut8 * d2;
                g_lat[er8 * 128 + n0 + 1] = cut8 * d3;
            }
        } else if (EPI == 3) {
            if (n0 < 32) {
                const int u = n0 >> 1;
                if (er0 < E) {
                    g_fs[er0 * 16 + u] = d0 * ea0[0];
                    g_fv[er0 * 48 + u * 3 + 0] = d1 * ea0[1];
                    g_fv[er0 * 48 + u * 3 + 1] = d1 * ea0[2];
                    g_fv[er0 * 48 + u * 3 + 2] = d1 * ea0[3];
                }
                if (er8 < E) {
                    g_fs[er8 * 16 + u] = d2 * ea8[0];
                    g_fv[er8 * 48 + u * 3 + 0] = d3 * ea8[1];
                    g_fv[er8 * 48 + u * 3 + 1] = d3 * ea8[2];
                    g_fv[er8 * 48 + u * 3 + 2] = d3 * ea8[3];
                }
            } else {
                const int u = (n0 - 32) >> 1;
                if (er0 < E) {
                    atomicAdd(&g_env_s[c0 * 16 + u], d0 * ea0[0]);
                    atomicAdd(&g_env_v[c0 * 48 + u * 3 + 0], d1 * ea0[1]);
                    atomicAdd(&g_env_v[c0 * 48 + u * 3 + 1], d1 * ea0[2]);
                    atomicAdd(&g_env_v[c0 * 48 + u * 3 + 2], d1 * ea0[3]);
                }
                if (er8 < E) {
                    atomicAdd(&g_env_s[c8 * 16 + u], d2 * ea8[0]);
                    atomicAdd(&g_env_v[c8 * 48 + u * 3 + 0], d3 * ea8[1]);
                    atomicAdd(&g_env_v[c8 * 48 + u * 3 + 1], d3 * ea8[2]);
                    atomicAdd(&g_env_v[c8 * 48 + u * 3 + 2], d3 * ea8[3]);
                }
            }
        } else if (EPI == 4) {
            const int u = n0 >> 1;
            if (er0 < E) {
                atomicAdd(&g_env_s[c0 * 16 + u], d0 * ea0[0]);
                atomicAdd(&g_env_v[c0 * 48 + u * 3 + 0], d1 * ea0[1]);
                atomicAdd(&g_env_v[c0 * 48 + u * 3 + 1], d1 * ea0[2]);
                atomicAdd(&g_env_v[c0 * 48 + u * 3 + 2], d1 * ea0[3]);
            }
            if (er8 < E) {
                atomicAdd(&g_env_s[c8 * 16 + u], d2 * ea8[0]);
                atomicAdd(&g_env_v[c8 * 48 + u * 3 + 0], d3 * ea8[1]);
                atomicAdd(&g_env_v[c8 * 48 + u * 3 + 1], d3 * ea8[2]);
                atomicAdd(&g_env_v[c8 * 48 + u * 3 + 2], d3 * ea8[3]);
            }
        } else {
            if (er0 < E) {
                const float* f0 = &g_fv[er0 * 48 + n0 * 3];
#pragma unroll
                for (int i = 0; i < 3; i++)
                    o0[i] += d0 * f0[i] + d1 * f0[3 + i];
            }
            if (er8 < E) {
                const float* f8 = &g_fv[er8 * 48 + n0 * 3];
#pragma unroll
                for (int i = 0; i < 3; i++)
                    o8[i] += d2 * f8[i] + d3 * f8[3 + i];
            }
        }
    }

    if (EPI == 5) {
#pragma unroll
        for (int i = 0; i < 3; i++) {
            o0[i] += __shfl_xor_sync(0xffffffffu, o0[i], 1);
            o0[i] += __shfl_xor_sync(0xffffffffu, o0[i], 2);
            o8[i] += __shfl_xor_sync(0xffffffffu, o8[i], 1);
            o8[i] += __shfl_xor_sync(0xffffffffu, o8[i], 2);
        }
        if (q == 0) {
            if (er0 < E) {
                Y[er0 * 3 + 0] = INV_SM * o0[0];
                Y[er0 * 3 + 1] = INV_SM * o0[1];
                Y[er0 * 3 + 2] = INV_SM * o0[2];
            }
            if (er8 < E) {
                Y[er8 * 3 + 0] = INV_SM * o8[0];
                Y[er8 * 3 + 1] = INV_SM * o8[1];
                Y[er8 * 3 + 2] = INV_SM * o8[2];
            }
        }
    }
}

// ---------------- mma.sync tf32 fused l2w (R14 exact: 2-way ks-split GEMM2) --------
#define H_STR  132
#define SM_SS  (256 * H_STR)
#define SM_VS  (SM_SS + 256 * 33)
#define L2W_SMEM_B ((SM_VS + 256 * 25) * 4)

__device__ __forceinline__ float l2w_xval(int e, int k, int E) {
    if (e >= E) return 0.f;
    const float v = (k < 128) ? g_lat[e * 128 + k] : g_scal[e * 32 + (k - 128)];
    return tf32r(v);
}
__device__ __forceinline__ float l2w_xval_f(int e, int k) {
    const float v = (k < 128) ? g_lat[e * 128 + k] : g_scal[e * 32 + (k - 128)];
    return tf32r(v);
}

__global__ void __launch_bounds__(256, 1)
k_l2w_ts(const float* __restrict__ w1f, const float* __restrict__ w2f, int E) {
    extern __shared__ float sm[];
    float* Hs = sm;
    float* Ss = sm + SM_SS;
    float* Vs = sm + SM_VS;
    const int t = threadIdx.x, lane = t & 31, w = t >> 5;
    const int g = lane >> 2, q = lane & 3;
    const int e0 = blockIdx.x * 256;
    const int rb = w * 32;
    const bool full = (e0 + 256 <= E);

    for (int idx = t; idx < 256 * 32; idx += 256) {
        const int el = idx >> 5, pu = idx & 31;
        const int e = e0 + el;
        Ss[el * 33 + pu] = (e < E) ? g_scal[e * 32 + 2 * (pu & 15) + (pu >> 4)] : 0.f;
    }
    __syncthreads();

    {
        float acc[16][8];
#pragma unroll
        for (int c = 0; c < 16; c++)
#pragma unroll
            for (int j = 0; j < 8; j++) acc[c][j] = 0.f;

#pragma unroll 1
        for (int ks = 0; ks < 20; ks++) {
            const int k0 = ks * 8;
            uint32_t a[2][4];
            if (full) {
#pragma unroll
                for (int m = 0; m < 2; m++) {
                    const int er0 = e0 + rb + 16 * m + g;
                    a[m][0] = fbits(l2w_xval_f(er0,     k0 + q));
                    a[m][1] = fbits(l2w_xval_f(er0 + 8, k0 + q));
                    a[m][2] = fbits(l2w_xval_f(er0,     k0 + q + 4));
                    a[m][3] = fbits(l2w_xval_f(er0 + 8, k0 + q + 4));
                }
            } else {
#pragma unroll
                for (int m = 0; m < 2; m++) {
                    const int er0 = e0 + rb + 16 * m + g;
                    a[m][0] = fbits(l2w_xval(er0,     k0 + q,     E));
                    a[m][1] = fbits(l2w_xval(er0 + 8, k0 + q,     E));
                    a[m][2] = fbits(l2w_xval(er0,     k0 + q + 4, E));
                    a[m][3] = fbits(l2w_xval(er0 + 8, k0 + q + 4, E));
                }
            }
#pragma unroll
            for (int ch = 0; ch < 16; ch++) {
                const float2 b = *reinterpret_cast<const float2*>(
                    &w1f[(ch * 20 + ks) * 64 + lane * 2]);
                mma_tf32(acc[ch][0], acc[ch][1], acc[ch][2], acc[ch][3],
                         a[0][0], a[0][1], a[0][2], a[0][3], fbits(b.x), fbits(b.y));
                mma_tf32(acc[ch][4], acc[ch][5], acc[ch][6], acc[ch][7],
                         a[1][0], a[1][1], a[1][2], a[1][3], fbits(b.x), fbits(b.y));
            }
        }
#pragma unroll
        for (int ch = 0; ch < 16; ch++) {
#pragma unroll
            for (int m = 0; m < 2; m++)
#pragma unroll
                for (int s = 0; s < 2; s++) {
                    const int row = rb + 16 * m + 8 * s + g;
                    const int col = ch * 8 + 2 * q;
                    Hs[row * H_STR + col]     = tf32r(silu_f(acc[ch][4 * m + 2 * s + 0]));
                    Hs[row * H_STR + col + 1] = tf32r(silu_f(acc[ch][4 * m + 2 * s + 1]));
                }
        }
        __syncwarp();
    }

    uint32_t Af[16][2][4];
#pragma unroll
    for (int ks = 0; ks < 16; ks++) {
        const int k0 = ks * 8;
#pragma unroll
        for (int m = 0; m < 2; m++) {
            const int r0 = rb + 16 * m + g;
            Af[ks][m][0] = fbits(Hs[r0 * H_STR + k0 + q]);
            Af[ks][m][1] = fbits(Hs[(r0 + 8) * H_STR + k0 + q]);
            Af[ks][m][2] = fbits(Hs[r0 * H_STR + k0 + q + 4]);
            Af[ks][m][3] = fbits(Hs[(r0 + 8) * H_STR + k0 + q + 4]);
        }
    }

    float fs[4][2][2];
    float fv[4][2][2][3];
#pragma unroll
    for (int rg = 0; rg < 4; rg++)
#pragma unroll
        for (int h = 0; h < 2; h++)
#pragma unroll
            for (int c = 0; c < 2; c++) {
                fs[rg][h][c] = 0.f;
                fv[rg][h][c][0] = 0.f; fv[rg][h][c][1] = 0.f; fv[rg][h][c][2] = 0.f;
            }

#pragma unroll 1
    for (int blk = 0; blk < 10; blk++) {
        if (blk >= 4) {
            __syncthreads();
            const int pb3 = (blk - 4) * 24;
            for (int idx = t; idx < 256 * 24; idx += 256) {
                const int el = idx / 24, c = idx - el * 24;
                const int e = e0 + el;
                Vs[el * 25 + c] = (e < E) ? g_V[e * 144 + pb3 + c] : 0.f;
            }
            __syncthreads();
        }
#pragma unroll 1
        for (int j = 0; j < 8; j++) {
            const int pu = blk * 8 + j;
#pragma unroll
            for (int h = 0; h < 2; h++) {
                // 2-way ks-split: 4 independent accumulator chains (R14 proven)
                float d[8], d2[8];
#pragma unroll
                for (int x = 0; x < 8; x++) { d[x] = 0.f; d2[x] = 0.f; }
                const int fb = ((pu * 2 + h) * 16) * 64;
#pragma unroll
                for (int ks = 0; ks < 8; ks++) {
                    const float2 b = *reinterpret_cast<const float2*>(
                        &w2f[fb + ks * 64 + lane * 2]);
                    mma_tf32(d[0], d[1], d[2], d[3],
                             Af[ks][0][0], Af[ks][0][1], Af[ks][0][2], Af[ks][0][3],
                             fbits(b.x), fbits(b.y));
                    mma_tf32(d[4], d[5], d[6], d[7],
                             Af[ks][1][0], Af[ks][1][1], Af[ks][1][2], Af[ks][1][3],
                             fbits(b.x), fbits(b.y));
                    const float2 b2 = *reinterpret_cast<const float2*>(
                        &w2f[fb + (ks + 8) * 64 + lane * 2]);
                    mma_tf32(d2[0], d2[1], d2[2], d2[3],
                             Af[ks + 8][0][0], Af[ks + 8][0][1], Af[ks + 8][0][2], Af[ks + 8][0][3],
                             fbits(b2.x), fbits(b2.y));
                    mma_tf32(d2[4], d2[5], d2[6], d2[7],
                             Af[ks + 8][1][0], Af[ks + 8][1][1], Af[ks + 8][1][2], Af[ks + 8][1][3],
                             fbits(b2.x), fbits(b2.y));
                }
#pragma unroll
                for (int x = 0; x < 8; x++) d[x] += d2[x];
                if (blk < 4) {
#pragma unroll
                    for (int rg = 0; rg < 4; rg++) {
                        const float s = Ss[(rb + rg * 8 + g) * 33 + pu];
                        fs[rg][h][0] = fmaf(s, d[2 * rg + 0], fs[rg][h][0]);
                        fs[rg][h][1] = fmaf(s, d[2 * rg + 1], fs[rg][h][1]);
                    }
                } else {
#pragma unroll
                    for (int rg = 0; rg < 4; rg++) {
                        const int base = (rb + rg * 8 + g) * 25 + j * 3;
                        const float v0 = Vs[base], v1 = Vs[base + 1], v2 = Vs[base + 2];
#pragma unroll
                        for (int c = 0; c < 2; c++) {
                            const float dd = d[2 * rg + c];
                            fv[rg][h][c][0] = fmaf(dd, v0, fv[rg][h][c][0]);
                            fv[rg][h][c][1] = fmaf(dd, v1, fv[rg][h][c][1]);
                            fv[rg][h][c][2] = fmaf(dd, v2, fv[rg][h][c][2]);
                        }
                    }
                }
            }
        }
    }

#pragma unroll
    for (int rg = 0; rg < 4; rg++) {
        const int e = e0 + rb + rg * 8 + g;
        if (e >= E) continue;
#pragma unroll
        for (int h = 0; h < 2; h++)
#pragma unroll
            for (int c = 0; c < 2; c++) {
                const int v = h * 8 + 2 * q + c;
                g_fs[e * 16 + v] = C_FS * fs[rg][h][c];
                g_fv[e * 48 + v * 3 + 0] = C_FV * fv[rg][h][c][0];
                g_fv[e * 48 + v * 3 + 1] = C_FV * fv[rg][h][c][1];
                g_fv[e * 48 + v * 3 + 2] = C_FV * fv[rg][h][c][2];
            }
    }
}

// ---------------- host driver ----------------
extern "C" void kernel_launch(void* const* d_in, const int* in_sizes, int n_in,
                              void* d_out, int out_size) {
    const float* edge_attr  = (const float*)d_in[0];
    const float* node_attrs = (const float*)d_in[1];
    const float* edge_embed = (const float*)d_in[2];
    const float* edge_u     = (const float*)d_in[3];
    const int*   edge_index = (const int*)d_in[4];
    const float* w2b1    = (const float*)d_in[5];
    const float* w2b2    = (const float*)d_in[6];
    const float* lat1_w1 = (const float*)d_in[7];
    const float* lat1_w2 = (const float*)d_in[8];
    const float* env0_w1 = (const float*)d_in[9];
    const float* env0_w2 = (const float*)d_in[10];
    const float* env1_w1 = (const float*)d_in[11];
    const float* env1_w2 = (const float*)d_in[12];
    const float* l2w0_w1 = (const float*)d_in[13];
    const float* l2w0_w2 = (const float*)d_in[14];
    const float* l2w1_w1 = (const float*)d_in[15];
    const float* l2w1_w2 = (const float*)d_in[16];
    const float* envlin_ws = (const float*)d_in[17];
    const float* envlin_wv = (const float*)d_in[18];
    const float* fl2w_w1 = (const float*)d_in[19];
    const float* fl2w_w2 = (const float*)d_in[20];
    float* out = (float*)d_out;

    const int E = in_sizes[0] / 4;
    const int N = in_sizes[1] / 4;
    if (E > MAX_E || N > MAX_N) return;

    float *p_lat, *p_scal, *p_w1f, *p_w2f;
    cudaGetSymbolAddress((void**)&p_lat, g_lat);
    cudaGetSymbolAddress((void**)&p_scal, g_scal);
    cudaGetSymbolAddress((void**)&p_w1f, g_w1f);
    cudaGetSymbolAddress((void**)&p_w2f, g_w2f);

    const int smM160 = 128 * 165 * 4;
    const int smM128 = 128 * 133 * 4;

    cudaFuncSetAttribute((const void*)k_mlp_tc<16, 2,16,2,2>, cudaFuncAttributeMaxDynamicSharedMemorySize, smM128);
    cudaFuncSetAttribute((const void*)k_mlp_tc<128,16, 8,0,3>, cudaFuncAttributeMaxDynamicSharedMemorySize, smM128);
    cudaFuncSetAttribute((const void*)k_mlp_tc<160,20,16,1,1>, cudaFuncAttributeMaxDynamicSharedMemorySize, smM160);
    cudaFuncSetAttribute((const void*)k_mlp_tc<128,16, 4,0,4>, cudaFuncAttributeMaxDynamicSharedMemorySize, smM128);
    cudaFuncSetAttribute((const void*)k_mlp_tc<160,20, 2,1,5>, cudaFuncAttributeMaxDynamicSharedMemorySize, smM160);
    cudaFuncSetAttribute((const void*)k_l2w_ts, cudaFuncAttributeMaxDynamicSharedMemorySize, L2W_SMEM_B);

    const int nbM   = (E + 127) / 128;
    const int nb256 = (E + 255) / 256;
    const int nbCZ  = (((E * 16 > MAX_N * 64) ? E * 16 : MAX_N * 64) + 255) / 256;

    auto packN = [](int KS1, int NCH2, int zero) {
        return ((16 * KS1 + NCH2 * 16) * 32 + (zero ? MAX_N * 64 : 0) + 255) / 256;
    };

    // ---- stage 0: pack l2w weights (both layers, out of critical path) + first MLP ----
    k_pack_w1<<<(16 * 20 * 64 + 255) / 256, 256>>>(l2w0_w1, p_w1f);
    k_pack_w2<<<(80 * 2 * 16 * 64 + 255) / 256, 256>>>(l2w0_w2, p_w2f);
    k_pack_w1<<<(16 * 20 * 64 + 255) / 256, 256>>>(l2w1_w1, p_w1f + 20480);
    k_pack_w2<<<(80 * 2 * 16 * 64 + 255) / 256, 256>>>(l2w1_w2, p_w2f + 163840);
    k_pack_mlp<<<packN(2, 16, 0), 256>>>(w2b1, 2, w2b2, 16, 128, 0);
    k_mlp_tc<16, 2,16,2,2><<<nbM, 256, smM128>>>(node_attrs, edge_embed, edge_u, edge_index, edge_attr, p_lat, E);

    // ---- layer 0: env0 MLP (fused weighter+scatter); pack also zeroes env ----
    k_pack_mlp<<<packN(16, 8, 1), 256>>>(env0_w1, 16, env0_w2, 8, 64, 1);
    k_mlp_tc<128,16, 8,0,3><<<nbM, 256, smM128>>>(p_lat, p_lat, edge_u, edge_index, edge_attr, nullptr, E);
    k_envlin<<<(N * 16 + 255) / 256, 256>>>(envlin_ws, envlin_wv, N);
    k_combine<<<nbCZ, 256>>>(edge_index, E, 1);
    k_l2w_ts<<<nb256, 256, L2W_SMEM_B>>>(p_w1f, p_w2f, E);

    // ---- layer 1 ----
    k_pack_mlp<<<packN(20, 16, 0), 256>>>(lat1_w1, 20, lat1_w2, 16, 128, 0);
    k_mlp_tc<160,20,16,1,1><<<nbM, 256, smM160>>>(p_lat, p_scal, edge_u, edge_index, edge_attr, p_lat, E);
    k_pack_mlp<<<packN(16, 4, 0), 256>>>(env1_w1, 16, env1_w2, 4, 32, 0);
    k_mlp_tc<128,16, 4,0,4><<<nbM, 256, smM128>>>(p_lat, p_lat, edge_u, edge_index, edge_attr, nullptr, E);
    k_envlin<<<(N * 16 + 255) / 256, 256>>>(envlin_ws + 256, envlin_wv + 256, N);
    k_combine<<<nbCZ, 256>>>(edge_index, E, 0);
    k_l2w_ts<<<nb256, 256, L2W_SMEM_B>>>(p_w1f + 20480, p_w2f + 163840, E);

    // ---- final: fw MLP with fused output contraction ----
    k_pack_mlp<<<packN(20, 2, 0), 256>>>(fl2w_w1, 20, fl2w_w2, 2, 16, 0);
    k_mlp_tc<160,20, 2,1,5><<<nbM, 256, smM160>>>(p_lat, p_scal, edge_u, edge_index, edge_attr, out, E);
}

// round 17
// speedup vs baseline: 1.0744x; 1.0744x over previous
#include <cuda_runtime.h>
#include <cstdint>

// ---------------- problem constants ----------------
#define MAX_E 120000
#define MAX_N 5000

typedef unsigned long long u64;

// ---------------- scratch (static __device__, allocation-free) ----------------
__device__ float g_cut[MAX_E];
__device__ float g_lat[MAX_E * 128];
__device__ float g_fs[MAX_E * 16];
__device__ float g_fv[MAX_E * 48];
__device__ float g_scal[MAX_E * 32];
__device__ float g_V[MAX_E * 144];
__device__ float g_env_s[MAX_N * 16];
__device__ float g_env_v[MAX_N * 48];
__device__ float g_env_s2[MAX_N * 16];
__device__ float g_env_v2[MAX_N * 48];
__device__ float g_w1f[16 * 20 * 64];      // l2w W1 frag-packed (current layer)
__device__ float g_w2f[80 * 2 * 16 * 64];  // l2w W2 frag-packed (current layer)
__device__ float g_mw1f[16 * 20 * 128];    // MLP W1 frag-packed hi/lo
__device__ float g_mw2f[16 * 16 * 128];    // MLP W2 frag-packed hi/lo

// ---------------- math constants ----------------
constexpr float C_OLD    = 0.8944271909999159f;
constexpr float A_C_OLD  = 0.4472135954999579f;
constexpr float INV_S3   = 0.5773502691896258f;
constexpr float INV_S2   = 0.7071067811865476f;
constexpr float C_FS     = 0.17677669529663687f;
constexpr float C_FV     = 0.14433756729740643f;
constexpr float NORM_LIN = 0.05590169943749474f;
constexpr float INV_SM   = 0.25f;

__device__ __forceinline__ float silu_f(float x) { return x / (1.f + __expf(-x)); }

// ---------------- tf32 helpers ----------------
__device__ __forceinline__ float tf32r(float x) {
    uint32_t u;
    asm("cvt.rna.tf32.f32 %0, %1;" : "=r"(u) : "f"(x));
    return __uint_as_float(u);
}
__device__ __forceinline__ void mma_tf32(float& d0, float& d1, float& d2, float& d3,
                                         uint32_t a0, uint32_t a1, uint32_t a2, uint32_t a3,
                                         uint32_t b0, uint32_t b1) {
    asm volatile(
        "mma.sync.aligned.m16n8k8.row.col.f32.tf32.tf32.f32 "
        "{%0,%1,%2,%3}, {%4,%5,%6,%7}, {%8,%9}, {%0,%1,%2,%3};"
        : "+f"(d0), "+f"(d1), "+f"(d2), "+f"(d3)
        : "r"(a0), "r"(a1), "r"(a2), "r"(a3), "r"(b0), "r"(b1));
}
__device__ __forceinline__ uint32_t fbits(float x) { return __float_as_uint(x); }

// ---------------- per-node / per-edge helper kernels ----------------
__global__ void k_envlin(const float* __restrict__ Ws, const float* __restrict__ Wv, int N) {
    const int idx = blockIdx.x * blockDim.x + threadIdx.x;
    if (idx >= N * 16) return;
    const int n = idx >> 4, v = idx & 15;
    float s = 0.f, v0 = 0.f, v1 = 0.f, v2 = 0.f;
#pragma unroll
    for (int u = 0; u < 16; u++) {
        const float wsv = Ws[u * 16 + v];
        const float wvv = Wv[u * 16 + v];
        s  = fmaf(g_env_s[n * 16 + u], wsv, s);
        v0 = fmaf(g_env_v[n * 48 + u * 3 + 0], wvv, v0);
        v1 = fmaf(g_env_v[n * 48 + u * 3 + 1], wvv, v1);
        v2 = fmaf(g_env_v[n * 48 + u * 3 + 2], wvv, v2);
    }
    g_env_s2[n * 16 + v] = s * NORM_LIN;
    g_env_v2[n * 48 + v * 3 + 0] = v0 * NORM_LIN;
    g_env_v2[n * 48 + v * 3 + 1] = v1 * NORM_LIN;
    g_env_v2[n * 48 + v * 3 + 2] = v2 * NORM_LIN;
}

// zero_env: also clear env accumulators for the NEXT layer (this layer's envlin
// already consumed them earlier in stream order).
__global__ void k_combine(const int* __restrict__ edge_index, int E, int zero_env) {
    const int idx = blockIdx.x * blockDim.x + threadIdx.x;
    if (zero_env) {
        if (idx < MAX_N * 16) g_env_s[idx] = 0.f;
        else if (idx < MAX_N * 64) g_env_v[idx - MAX_N * 16] = 0.f;
    }
    if (idx >= E * 16) return;
    const int e = idx >> 4, u = idx & 15;
    const int c = edge_index[e];
    const float es  = g_env_s2[c * 16 + u];
    const float ev0 = g_env_v2[c * 48 + u * 3 + 0];
    const float ev1 = g_env_v2[c * 48 + u * 3 + 1];
    const float ev2 = g_env_v2[c * 48 + u * 3 + 2];
    const float fsv = g_fs[e * 16 + u];
    const float fv0 = g_fv[e * 48 + u * 3 + 0];
    const float fv1 = g_fv[e * 48 + u * 3 + 1];
    const float fv2 = g_fv[e * 48 + u * 3 + 2];

    g_scal[e * 32 + 2 * u]     = fsv * es;
    g_scal[e * 32 + 2 * u + 1] = (fv0 * ev0 + fv1 * ev1 + fv2 * ev2) * INV_S3;

    float* Vp = &g_V[e * 144];
    Vp[u * 3 + 0] = fsv * ev0;
    Vp[u * 3 + 1] = fsv * ev1;
    Vp[u * 3 + 2] = fsv * ev2;
    Vp[48 + u * 3 + 0] = fv0 * es;
    Vp[48 + u * 3 + 1] = fv1 * es;
    Vp[48 + u * 3 + 2] = fv2 * es;
    Vp[96 + u * 3 + 0] = (fv1 * ev2 - fv2 * ev1) * INV_S2;
    Vp[96 + u * 3 + 1] = (fv2 * ev0 - fv0 * ev2) * INV_S2;
    Vp[96 + u * 3 + 2] = (fv0 * ev1 - fv1 * ev0) * INV_S2;
}

// ---------------- l2w weight frag-packing: W1 + W2 in ONE launch ----------------
__global__ void k_pack_l2w(const float* __restrict__ W1, const float* __restrict__ W2) {
    int idx = blockIdx.x * blockDim.x + threadIdx.x;
    if (idx < 16 * 20 * 64) {
        const int frag = idx >> 6;
        const int r = idx & 63;
        const int lane = r >> 1, z = r & 1;
        const int ch = frag / 20, ks = frag % 20;
        const int n = ch * 8 + (lane >> 2);
        const int k = ks * 8 + (lane & 3) + z * 4;
        g_w1f[idx] = tf32r(W1[k * 128 + n]);
        return;
    }
    idx -= 16 * 20 * 64;
    if (idx >= 80 * 2 * 16 * 64) return;
    const int frag = idx >> 6;
    const int r = idx & 63;
    const int lane = r >> 1, z = r & 1;
    const int puh = frag >> 4, ks = frag & 15;
    const int pu = puh >> 1, h = puh & 1;
    const int n = pu * 16 + h * 8 + (lane >> 2);
    const int k = ks * 8 + (lane & 3) + z * 4;
    g_w2f[idx] = tf32r(W2[k * 1280 + n]);
}
#define PACK_L2W_THREADS (16 * 20 * 64 + 80 * 2 * 16 * 64)

// ---------------- MLP weight frag-packing (hi/lo for 3xTF32) ----------------
// zero_env: extra thread range clears env accumulators (fused memset).
__global__ void k_pack_mlp(const float* __restrict__ W1, int KS1,
                           const float* __restrict__ W2, int NCH2, int OUT,
                           int zero_env) {
    const int tid = blockIdx.x * blockDim.x + threadIdx.x;
    const int n1 = 16 * KS1;
    const int packTotal = (n1 + NCH2 * 16) * 32;
    if (tid >= packTotal) {
        if (zero_env) {
            const int z = tid - packTotal;
            if (z < MAX_N * 16) g_env_s[z] = 0.f;
            else if (z < MAX_N * 64) g_env_v[z - MAX_N * 16] = 0.f;
        }
        return;
    }
    const int frag = tid >> 5, lane = tid & 31;
    const float* W;
    float* dst;
    int ldn, fl, ch, ks;
    if (frag < n1) {
        W = W1; ldn = 128; dst = g_mw1f; fl = frag;
        ch = fl / KS1; ks = fl - ch * KS1;
    } else {
        W = W2; ldn = OUT; dst = g_mw2f; fl = frag - n1;
        ch = fl >> 4; ks = fl & 15;
    }
    const int n = ch * 8 + (lane >> 2);
    const int k = ks * 8 + (lane & 3);
    const float w0 = W[k * ldn + n];
    const float w1 = W[(k + 4) * ldn + n];
    const float h0 = tf32r(w0), h1 = tf32r(w1);
    float4 o;
    o.x = h0; o.y = h1;
    o.z = tf32r(w0 - h0); o.w = tf32r(w1 - h1);
    *reinterpret_cast<float4*>(&dst[fl * 128 + lane * 4]) = o;
}

// ---------------- tensor-core MLP: Y = silu(X@W1)@W2, 3xTF32 ----------
// STAGE: 0 = X=g_lat(128); 1 = X=[g_lat|g_scal](160); 2 = gather x2b(16) + cut.
// EPI:   0 = store Y;  1 = lat blend;  2 = cut-scale into g_lat;
//        3 = env0 fused; 4 = env1 fused; 5 = final fused output contraction.
template <int IN, int KS1, int NCH2, int STAGE, int EPI>
__global__ void __launch_bounds__(256, 2)
k_mlp_tc(const float* __restrict__ Xa, const float* __restrict__ Xb,
         const float* __restrict__ edge_u, const int* __restrict__ edge_index,
         const float* __restrict__ edge_attr,
         float* __restrict__ Y, int E) {
    constexpr int XSTR = (IN >= 128) ? IN + 5 : 133;
    constexpr int OUT = NCH2 * 8;
    extern __shared__ float sm[];
    float* Xs = sm;
    const int t = threadIdx.x, lane = t & 31, w = t >> 5;
    const int g = lane >> 2, q = lane & 3;
    const int e0 = blockIdx.x * 128;
    const bool full = (e0 + 128 <= E);

    if (STAGE == 2) {
        for (int idx = t; idx < 128 * 16; idx += 256) {
            const int le = idx >> 4, c = idx & 15;
            const int e = e0 + le;
            float v = 0.f;
            if (e < E) {
                if (c < 4)       v = Xa[edge_index[e] * 4 + c];
                else if (c < 8)  v = Xa[edge_index[E + e] * 4 + (c - 4)];
                else             v = Xb[e * 8 + (c - 8)];
            }
            Xs[le * XSTR + c] = v;
        }
        if (t < 128) {
            const int e = e0 + t;
            if (e < E) {
                const float u = edge_u[e];
                const float u2 = u * u, u3 = u2 * u, u6 = u3 * u3;
                const float f = 1.f - 28.f * u6 + 48.f * u6 * u - 21.f * u6 * u2;
                g_cut[e] = (u < 1.f) ? f : 0.f;
            }
        }
    } else if (full) {
        constexpr int C4 = IN / 4;
        for (int idx = t; idx < 128 * C4; idx += 256) {
            const int le = idx / C4, c4 = idx - le * C4;
            const int e = e0 + le;
            const int c = c4 * 4;
            float4 v;
            if (STAGE == 0 || c < 128) v = *reinterpret_cast<const float4*>(&Xa[e * 128 + c]);
            else                       v = *reinterpret_cast<const float4*>(&Xb[e * 32 + (c - 128)]);
            float* p = &Xs[le * XSTR + c];
            p[0] = v.x; p[1] = v.y; p[2] = v.z; p[3] = v.w;
        }
    } else {
        for (int idx = t; idx < 128 * IN; idx += 256) {
            const int le = idx / IN, c = idx - le * IN;
            const int e = e0 + le;
            float v = 0.f;
            if (e < E) v = (STAGE == 0 || c < 128) ? Xa[e * 128 + c] : Xb[e * 32 + (c - 128)];
            Xs[le * XSTR + c] = v;
        }
    }
    __syncthreads();

    const int r0 = w * 16 + g;

    // ---- GEMM1 ----
    {
        float acc[16][4];
#pragma unroll
        for (int c = 0; c < 16; c++)
#pragma unroll
            for (int j = 0; j < 4; j++) acc[c][j] = 0.f;

#pragma unroll 1
        for (int ks = 0; ks < KS1; ks++) {
            const int k0 = ks * 8;
            const float x0 = Xs[r0 * XSTR + k0 + q];
            const float x1 = Xs[(r0 + 8) * XSTR + k0 + q];
            const float x2 = Xs[r0 * XSTR + k0 + q + 4];
            const float x3 = Xs[(r0 + 8) * XSTR + k0 + q + 4];
            const float h0 = tf32r(x0), h1 = tf32r(x1), h2 = tf32r(x2), h3 = tf32r(x3);
            const uint32_t ah0 = fbits(h0), ah1 = fbits(h1), ah2 = fbits(h2), ah3 = fbits(h3);
            const uint32_t al0 = fbits(tf32r(x0 - h0)), al1 = fbits(tf32r(x1 - h1));
            const uint32_t al2 = fbits(tf32r(x2 - h2)), al3 = fbits(tf32r(x3 - h3));
#pragma unroll
            for (int ch = 0; ch < 16; ch++) {
                const float4 b = *reinterpret_cast<const float4*>(
                    &g_mw1f[(ch * KS1 + ks) * 128 + lane * 4]);
                const uint32_t bh0 = fbits(b.x), bh1 = fbits(b.y);
                const uint32_t bl0 = fbits(b.z), bl1 = fbits(b.w);
                mma_tf32(acc[ch][0], acc[ch][1], acc[ch][2], acc[ch][3],
                         al0, al1, al2, al3, bh0, bh1);
                mma_tf32(acc[ch][0], acc[ch][1], acc[ch][2], acc[ch][3],
                         ah0, ah1, ah2, ah3, bl0, bl1);
                mma_tf32(acc[ch][0], acc[ch][1], acc[ch][2], acc[ch][3],
                         ah0, ah1, ah2, ah3, bh0, bh1);
            }
        }
        __syncwarp();
#pragma unroll
        for (int ch = 0; ch < 16; ch++) {
            const int col = ch * 8 + 2 * q;
            Xs[r0 * XSTR + col]           = silu_f(acc[ch][0]);
            Xs[r0 * XSTR + col + 1]       = silu_f(acc[ch][1]);
            Xs[(r0 + 8) * XSTR + col]     = silu_f(acc[ch][2]);
            Xs[(r0 + 8) * XSTR + col + 1] = silu_f(acc[ch][3]);
        }
        __syncwarp();
    }

    // ---- GEMM2: ks outer / ch inner ----
    float acc2[NCH2][4];
#pragma unroll
    for (int c = 0; c < NCH2; c++)
#pragma unroll
        for (int j = 0; j < 4; j++) acc2[c][j] = 0.f;

#pragma unroll 1
    for (int ks = 0; ks < 16; ks++) {
        const int k0 = ks * 8;
        const float x0 = Xs[r0 * XSTR + k0 + q];
        const float x1 = Xs[(r0 + 8) * XSTR + k0 + q];
        const float x2 = Xs[r0 * XSTR + k0 + q + 4];
        const float x3 = Xs[(r0 + 8) * XSTR + k0 + q + 4];
        const float h0 = tf32r(x0), h1 = tf32r(x1), h2 = tf32r(x2), h3 = tf32r(x3);
        const uint32_t ah0 = fbits(h0), ah1 = fbits(h1), ah2 = fbits(h2), ah3 = fbits(h3);
        const uint32_t al0 = fbits(tf32r(x0 - h0)), al1 = fbits(tf32r(x1 - h1));
        const uint32_t al2 = fbits(tf32r(x2 - h2)), al3 = fbits(tf32r(x3 - h3));
#pragma unroll
        for (int ch = 0; ch < NCH2; ch++) {
            const float4 b = *reinterpret_cast<const float4*>(
                &g_mw2f[(ch * 16 + ks) * 128 + lane * 4]);
            const uint32_t bh0 = fbits(b.x), bh1 = fbits(b.y);
            const uint32_t bl0 = fbits(b.z), bl1 = fbits(b.w);
            mma_tf32(acc2[ch][0], acc2[ch][1], acc2[ch][2], acc2[ch][3],
                     al0, al1, al2, al3, bh0, bh1);
            mma_tf32(acc2[ch][0], acc2[ch][1], acc2[ch][2], acc2[ch][3],
                     ah0, ah1, ah2, ah3, bl0, bl1);
            mma_tf32(acc2[ch][0], acc2[ch][1], acc2[ch][2], acc2[ch][3],
                     ah0, ah1, ah2, ah3, bh0, bh1);
        }
    }

    // ---- epilogue ----
    const int er0 = e0 + r0, er8 = er0 + 8;
    float cut0 = 0.f, cut8 = 0.f;
    if (EPI == 1 || EPI == 2) {
        cut0 = (er0 < E) ? g_cut[er0] : 0.f;
        cut8 = (er8 < E) ? g_cut[er8] : 0.f;
    }
    float ea0[4] = {0.f, 0.f, 0.f, 0.f}, ea8[4] = {0.f, 0.f, 0.f, 0.f};
    int c0 = 0, c8 = 0;
    if (EPI == 3 || EPI == 4) {
        if (er0 < E) {
            const float4 a = *reinterpret_cast<const float4*>(&edge_attr[er0 * 4]);
            ea0[0] = a.x; ea0[1] = a.y; ea0[2] = a.z; ea0[3] = a.w;
            c0 = edge_index[er0];
        }
        if (er8 < E) {
            const float4 a = *reinterpret_cast<const float4*>(&edge_attr[er8 * 4]);
            ea8[0] = a.x; ea8[1] = a.y; ea8[2] = a.z; ea8[3] = a.w;
            c8 = edge_index[er8];
        }
    }
    float o0[3] = {0.f, 0.f, 0.f}, o8[3] = {0.f, 0.f, 0.f};

#pragma unroll
    for (int ch = 0; ch < NCH2; ch++) {
        const int n0 = ch * 8 + 2 * q;
        const float d0 = acc2[ch][0], d1 = acc2[ch][1];
        const float d2 = acc2[ch][2], d3 = acc2[ch][3];
        if (EPI == 0) {
            if (er0 < E) { Y[er0 * OUT + n0] = d0; Y[er0 * OUT + n0 + 1] = d1; }
            if (er8 < E) { Y[er8 * OUT + n0] = d2; Y[er8 * OUT + n0 + 1] = d3; }
        } else if (EPI == 1) {
            if (er0 < E) {
                float* p = &g_lat[er0 * 128 + n0];
                p[0] = C_OLD * p[0] + A_C_OLD * cut0 * d0;
                p[1] = C_OLD * p[1] + A_C_OLD * cut0 * d1;
            }
            if (er8 < E) {
                float* p = &g_lat[er8 * 128 + n0];
                p[0] = C_OLD * p[0] + A_C_OLD * cut8 * d2;
                p[1] = C_OLD * p[1] + A_C_OLD * cut8 * d3;
            }
        } else if (EPI == 2) {
            if (er0 < E) {
                g_lat[er0 * 128 + n0]     = cut0 * d0;
                g_lat[er0 * 128 + n0 + 1] = cut0 * d1;
            }
            if (er8 < E) {
                g_lat[er8 * 128 + n0]     = cut8 * d2;
                g_lat[er8 * 128 + n0 + 1] = cut8 * d3;
            }
        } else if (EPI == 3) {
            if (n0 < 32) {
                const int u = n0 >> 1;
                if (er0 < E) {
                    g_fs[er0 * 16 + u] = d0 * ea0[0];
                    g_fv[er0 * 48 + u * 3 + 0] = d1 * ea0[1];
                    g_fv[er0 * 48 + u * 3 + 1] = d1 * ea0[2];
                    g_fv[er0 * 48 + u * 3 + 2] = d1 * ea0[3];
                }
                if (er8 < E) {
                    g_fs[er8 * 16 + u] = d2 * ea8[0];
                    g_fv[er8 * 48 + u * 3 + 0] = d3 * ea8[1];
                    g_fv[er8 * 48 + u * 3 + 1] = d3 * ea8[2];
                    g_fv[er8 * 48 + u * 3 + 2] = d3 * ea8[3];
                }
            } else {
                const int u = (n0 - 32) >> 1;
                if (er0 < E) {
                    atomicAdd(&g_env_s[c0 * 16 + u], d0 * ea0[0]);
                    atomicAdd(&g_env_v[c0 * 48 + u * 3 + 0], d1 * ea0[1]);
                    atomicAdd(&g_env_v[c0 * 48 + u * 3 + 1], d1 * ea0[2]);
                    atomicAdd(&g_env_v[c0 * 48 + u * 3 + 2], d1 * ea0[3]);
                }
                if (er8 < E) {
                    atomicAdd(&g_env_s[c8 * 16 + u], d2 * ea8[0]);
                    atomicAdd(&g_env_v[c8 * 48 + u * 3 + 0], d3 * ea8[1]);
                    atomicAdd(&g_env_v[c8 * 48 + u * 3 + 1], d3 * ea8[2]);
                    atomicAdd(&g_env_v[c8 * 48 + u * 3 + 2], d3 * ea8[3]);
                }
            }
        } else if (EPI == 4) {
            const int u = n0 >> 1;
            if (er0 < E) {
                atomicAdd(&g_env_s[c0 * 16 + u], d0 * ea0[0]);
                atomicAdd(&g_env_v[c0 * 48 + u * 3 + 0], d1 * ea0[1]);
                atomicAdd(&g_env_v[c0 * 48 + u * 3 + 1], d1 * ea0[2]);
                atomicAdd(&g_env_v[c0 * 48 + u * 3 + 2], d1 * ea0[3]);
            }
            if (er8 < E) {
                atomicAdd(&g_env_s[c8 * 16 + u], d2 * ea8[0]);
                atomicAdd(&g_env_v[c8 * 48 + u * 3 + 0], d3 * ea8[1]);
                atomicAdd(&g_env_v[c8 * 48 + u * 3 + 1], d3 * ea8[2]);
                atomicAdd(&g_env_v[c8 * 48 + u * 3 + 2], d3 * ea8[3]);
            }
        } else {
            if (er0 < E) {
                const float* f0 = &g_fv[er0 * 48 + n0 * 3];
#pragma unroll
                for (int i = 0; i < 3; i++)
                    o0[i] += d0 * f0[i] + d1 * f0[3 + i];
            }
            if (er8 < E) {
                const float* f8 = &g_fv[er8 * 48 + n0 * 3];
#pragma unroll
                for (int i = 0; i < 3; i++)
                    o8[i] += d2 * f8[i] + d3 * f8[3 + i];
            }
        }
    }

    if (EPI == 5) {
#pragma unroll
        for (int i = 0; i < 3; i++) {
            o0[i] += __shfl_xor_sync(0xffffffffu, o0[i], 1);
            o0[i] += __shfl_xor_sync(0xffffffffu, o0[i], 2);
            o8[i] += __shfl_xor_sync(0xffffffffu, o8[i], 1);
            o8[i] += __shfl_xor_sync(0xffffffffu, o8[i], 2);
        }
        if (q == 0) {
            if (er0 < E) {
                Y[er0 * 3 + 0] = INV_SM * o0[0];
                Y[er0 * 3 + 1] = INV_SM * o0[1];
                Y[er0 * 3 + 2] = INV_SM * o0[2];
            }
            if (er8 < E) {
                Y[er8 * 3 + 0] = INV_SM * o8[0];
                Y[er8 * 3 + 1] = INV_SM * o8[1];
                Y[er8 * 3 + 2] = INV_SM * o8[2];
            }
        }
    }
}

// ---------------- mma.sync tf32 fused l2w (R14 exact: 2-way ks-split GEMM2) --------
#define H_STR  132
#define SM_SS  (256 * H_STR)
#define SM_VS  (SM_SS + 256 * 33)
#define L2W_SMEM_B ((SM_VS + 256 * 25) * 4)

__device__ __forceinline__ float l2w_xval(int e, int k, int E) {
    if (e >= E) return 0.f;
    const float v = (k < 128) ? g_lat[e * 128 + k] : g_scal[e * 32 + (k - 128)];
    return tf32r(v);
}
__device__ __forceinline__ float l2w_xval_f(int e, int k) {
    const float v = (k < 128) ? g_lat[e * 128 + k] : g_scal[e * 32 + (k - 128)];
    return tf32r(v);
}

__global__ void __launch_bounds__(256, 1)
k_l2w_ts(int E) {
    extern __shared__ float sm[];
    float* Hs = sm;
    float* Ss = sm + SM_SS;
    float* Vs = sm + SM_VS;
    const int t = threadIdx.x, lane = t & 31, w = t >> 5;
    const int g = lane >> 2, q = lane & 3;
    const int e0 = blockIdx.x * 256;
    const int rb = w * 32;
    const bool full = (e0 + 256 <= E);

    for (int idx = t; idx < 256 * 32; idx += 256) {
        const int el = idx >> 5, pu = idx & 31;
        const int e = e0 + el;
        Ss[el * 33 + pu] = (e < E) ? g_scal[e * 32 + 2 * (pu & 15) + (pu >> 4)] : 0.f;
    }
    __syncthreads();

    {
        float acc[16][8];
#pragma unroll
        for (int c = 0; c < 16; c++)
#pragma unroll
            for (int j = 0; j < 8; j++) acc[c][j] = 0.f;

#pragma unroll 1
        for (int ks = 0; ks < 20; ks++) {
            const int k0 = ks * 8;
            uint32_t a[2][4];
            if (full) {
#pragma unroll
                for (int m = 0; m < 2; m++) {
                    const int er0 = e0 + rb + 16 * m + g;
                    a[m][0] = fbits(l2w_xval_f(er0,     k0 + q));
                    a[m][1] = fbits(l2w_xval_f(er0 + 8, k0 + q));
                    a[m][2] = fbits(l2w_xval_f(er0,     k0 + q + 4));
                    a[m][3] = fbits(l2w_xval_f(er0 + 8, k0 + q + 4));
                }
            } else {
#pragma unroll
                for (int m = 0; m < 2; m++) {
                    const int er0 = e0 + rb + 16 * m + g;
                    a[m][0] = fbits(l2w_xval(er0,     k0 + q,     E));
                    a[m][1] = fbits(l2w_xval(er0 + 8, k0 + q,     E));
                    a[m][2] = fbits(l2w_xval(er0,     k0 + q + 4, E));
                    a[m][3] = fbits(l2w_xval(er0 + 8, k0 + q + 4, E));
                }
            }
#pragma unroll
            for (int ch = 0; ch < 16; ch++) {
                const float2 b = *reinterpret_cast<const float2*>(
                    &g_w1f[(ch * 20 + ks) * 64 + lane * 2]);
                mma_tf32(acc[ch][0], acc[ch][1], acc[ch][2], acc[ch][3],
                         a[0][0], a[0][1], a[0][2], a[0][3], fbits(b.x), fbits(b.y));
                mma_tf32(acc[ch][4], acc[ch][5], acc[ch][6], acc[ch][7],
                         a[1][0], a[1][1], a[1][2], a[1][3], fbits(b.x), fbits(b.y));
            }
        }
#pragma unroll
        for (int ch = 0; ch < 16; ch++) {
#pragma unroll
            for (int m = 0; m < 2; m++)
#pragma unroll
                for (int s = 0; s < 2; s++) {
                    const int row = rb + 16 * m + 8 * s + g;
                    const int col = ch * 8 + 2 * q;
                    Hs[row * H_STR + col]     = tf32r(silu_f(acc[ch][4 * m + 2 * s + 0]));
                    Hs[row * H_STR + col + 1] = tf32r(silu_f(acc[ch][4 * m + 2 * s + 1]));
                }
        }
        __syncwarp();
    }

    uint32_t Af[16][2][4];
#pragma unroll
    for (int ks = 0; ks < 16; ks++) {
        const int k0 = ks * 8;
#pragma unroll
        for (int m = 0; m < 2; m++) {
            const int r0 = rb + 16 * m + g;
            Af[ks][m][0] = fbits(Hs[r0 * H_STR + k0 + q]);
            Af[ks][m][1] = fbits(Hs[(r0 + 8) * H_STR + k0 + q]);
            Af[ks][m][2] = fbits(Hs[r0 * H_STR + k0 + q + 4]);
            Af[ks][m][3] = fbits(Hs[(r0 + 8) * H_STR + k0 + q + 4]);
        }
    }

    float fs[4][2][2];
    float fv[4][2][2][3];
#pragma unroll
    for (int rg = 0; rg < 4; rg++)
#pragma unroll
        for (int h = 0; h < 2; h++)
#pragma unroll
            for (int c = 0; c < 2; c++) {
                fs[rg][h][c] = 0.f;
                fv[rg][h][c][0] = 0.f; fv[rg][h][c][1] = 0.f; fv[rg][h][c][2] = 0.f;
            }

#pragma unroll 1
    for (int blk = 0; blk < 10; blk++) {
        if (blk >= 4) {
            __syncthreads();
            const int pb3 = (blk - 4) * 24;
            for (int idx = t; idx < 256 * 24; idx += 256) {
                const int el = idx / 24, c = idx - el * 24;
                const int e = e0 + el;
                Vs[el * 25 + c] = (e < E) ? g_V[e * 144 + pb3 + c] : 0.f;
            }
            __syncthreads();
        }
#pragma unroll 1
        for (int j = 0; j < 8; j++) {
            const int pu = blk * 8 + j;
#pragma unroll
            for (int h = 0; h < 2; h++) {
                // 2-way ks-split: 4 independent accumulator chains (R14 proven)
                float d[8], d2[8];
#pragma unroll
                for (int x = 0; x < 8; x++) { d[x] = 0.f; d2[x] = 0.f; }
                const int fb = ((pu * 2 + h) * 16) * 64;
#pragma unroll
                for (int ks = 0; ks < 8; ks++) {
                    const float2 b = *reinterpret_cast<const float2*>(
                        &g_w2f[fb + ks * 64 + lane * 2]);
                    mma_tf32(d[0], d[1], d[2], d[3],
                             Af[ks][0][0], Af[ks][0][1], Af[ks][0][2], Af[ks][0][3],
                             fbits(b.x), fbits(b.y));
                    mma_tf32(d[4], d[5], d[6], d[7],
                             Af[ks][1][0], Af[ks][1][1], Af[ks][1][2], Af[ks][1][3],
                             fbits(b.x), fbits(b.y));
                    const float2 b2 = *reinterpret_cast<const float2*>(
                        &g_w2f[fb + (ks + 8) * 64 + lane * 2]);
                    mma_tf32(d2[0], d2[1], d2[2], d2[3],
                             Af[ks + 8][0][0], Af[ks + 8][0][1], Af[ks + 8][0][2], Af[ks + 8][0][3],
                             fbits(b2.x), fbits(b2.y));
                    mma_tf32(d2[4], d2[5], d2[6], d2[7],
                             Af[ks + 8][1][0], Af[ks + 8][1][1], Af[ks + 8][1][2], Af[ks + 8][1][3],
                             fbits(b2.x), fbits(b2.y));
                }
#pragma unroll
                for (int x = 0; x < 8; x++) d[x] += d2[x];
                if (blk < 4) {
#pragma unroll
                    for (int rg = 0; rg < 4; rg++) {
                        const float s = Ss[(rb + rg * 8 + g) * 33 + pu];
                        fs[rg][h][0] = fmaf(s, d[2 * rg + 0], fs[rg][h][0]);
                        fs[rg][h][1] = fmaf(s, d[2 * rg + 1], fs[rg][h][1]);
                    }
                } else {
#pragma unroll
                    for (int rg = 0; rg < 4; rg++) {
                        const int base = (rb + rg * 8 + g) * 25 + j * 3;
                        const float v0 = Vs[base], v1 = Vs[base + 1], v2 = Vs[base + 2];
#pragma unroll
                        for (int c = 0; c < 2; c++) {
                            const float dd = d[2 * rg + c];
                            fv[rg][h][c][0] = fmaf(dd, v0, fv[rg][h][c][0]);
                            fv[rg][h][c][1] = fmaf(dd, v1, fv[rg][h][c][1]);
                            fv[rg][h][c][2] = fmaf(dd, v2, fv[rg][h][c][2]);
                        }
                    }
                }
            }
        }
    }

#pragma unroll
    for (int rg = 0; rg < 4; rg++) {
        const int e = e0 + rb + rg * 8 + g;
        if (e >= E) continue;
#pragma unroll
        for (int h = 0; h < 2; h++)
#pragma unroll
            for (int c = 0; c < 2; c++) {
                const int v = h * 8 + 2 * q + c;
                g_fs[e * 16 + v] = C_FS * fs[rg][h][c];
                g_fv[e * 48 + v * 3 + 0] = C_FV * fv[rg][h][c][0];
                g_fv[e * 48 + v * 3 + 1] = C_FV * fv[rg][h][c][1];
                g_fv[e * 48 + v * 3 + 2] = C_FV * fv[rg][h][c][2];
            }
    }
}

// ---------------- host driver ----------------
extern "C" void kernel_launch(void* const* d_in, const int* in_sizes, int n_in,
                              void* d_out, int out_size) {
    const float* edge_attr  = (const float*)d_in[0];
    const float* node_attrs = (const float*)d_in[1];
    const float* edge_embed = (const float*)d_in[2];
    const float* edge_u     = (const float*)d_in[3];
    const int*   edge_index = (const int*)d_in[4];
    const float* w2b1    = (const float*)d_in[5];
    const float* w2b2    = (const float*)d_in[6];
    const float* lat1_w1 = (const float*)d_in[7];
    const float* lat1_w2 = (const float*)d_in[8];
    const float* env0_w1 = (const float*)d_in[9];
    const float* env0_w2 = (const float*)d_in[10];
    const float* env1_w1 = (const float*)d_in[11];
    const float* env1_w2 = (const float*)d_in[12];
    const float* l2w0_w1 = (const float*)d_in[13];
    const float* l2w0_w2 = (const float*)d_in[14];
    const float* l2w1_w1 = (const float*)d_in[15];
    const float* l2w1_w2 = (const float*)d_in[16];
    const float* envlin_ws = (const float*)d_in[17];
    const float* envlin_wv = (const float*)d_in[18];
    const float* fl2w_w1 = (const float*)d_in[19];
    const float* fl2w_w2 = (const float*)d_in[20];
    float* out = (float*)d_out;

    const int E = in_sizes[0] / 4;
    const int N = in_sizes[1] / 4;
    if (E > MAX_E || N > MAX_N) return;

    float *p_lat, *p_scal;
    cudaGetSymbolAddress((void**)&p_lat, g_lat);
    cudaGetSymbolAddress((void**)&p_scal, g_scal);

    const int smM160 = 128 * 165 * 4;
    const int smM128 = 128 * 133 * 4;

    cudaFuncSetAttribute((const void*)k_mlp_tc<16, 2,16,2,2>, cudaFuncAttributeMaxDynamicSharedMemorySize, smM128);
    cudaFuncSetAttribute((const void*)k_mlp_tc<128,16, 8,0,3>, cudaFuncAttributeMaxDynamicSharedMemorySize, smM128);
    cudaFuncSetAttribute((const void*)k_mlp_tc<160,20,16,1,1>, cudaFuncAttributeMaxDynamicSharedMemorySize, smM160);
    cudaFuncSetAttribute((const void*)k_mlp_tc<128,16, 4,0,4>, cudaFuncAttributeMaxDynamicSharedMemorySize, smM128);
    cudaFuncSetAttribute((const void*)k_mlp_tc<160,20, 2,1,5>, cudaFuncAttributeMaxDynamicSharedMemorySize, smM160);
    cudaFuncSetAttribute((const void*)k_l2w_ts, cudaFuncAttributeMaxDynamicSharedMemorySize, L2W_SMEM_B);

    const int nbM   = (E + 127) / 128;
    const int nb256 = (E + 255) / 256;
    const int nbCZ  = (((E * 16 > MAX_N * 64) ? E * 16 : MAX_N * 64) + 255) / 256;

    auto packN = [](int KS1, int NCH2, int zero) {
        return ((16 * KS1 + NCH2 * 16) * 32 + (zero ? MAX_N * 64 : 0) + 255) / 256;
    };

    // ---- stage 0: first MLP (gather, cut-scale epi) ----
    k_pack_mlp<<<packN(2, 16, 0), 256>>>(w2b1, 2, w2b2, 16, 128, 0);
    k_mlp_tc<16, 2,16,2,2><<<nbM, 256, smM128>>>(node_attrs, edge_embed, edge_u, edge_index, edge_attr, p_lat, E);

    // ---- layer 0: env0 MLP (fused weighter+scatter); pack also zeroes env ----
    k_pack_mlp<<<packN(16, 8, 1), 256>>>(env0_w1, 16, env0_w2, 8, 64, 1);
    k_mlp_tc<128,16, 8,0,3><<<nbM, 256, smM128>>>(p_lat, p_lat, edge_u, edge_index, edge_attr, nullptr, E);
    k_envlin<<<(N * 16 + 255) / 256, 256>>>(envlin_ws, envlin_wv, N);
    k_combine<<<nbCZ, 256>>>(edge_index, E, 1);
    k_pack_l2w<<<(PACK_L2W_THREADS + 255) / 256, 256>>>(l2w0_w1, l2w0_w2);
    k_l2w_ts<<<nb256, 256, L2W_SMEM_B>>>(E);

    // ---- layer 1 ----
    k_pack_mlp<<<packN(20, 16, 0), 256>>>(lat1_w1, 20, lat1_w2, 16, 128, 0);
    k_mlp_tc<160,20,16,1,1><<<nbM, 256, smM160>>>(p_lat, p_scal, edge_u, edge_index, edge_attr, p_lat, E);
    k_pack_mlp<<<packN(16, 4, 0), 256>>>(env1_w1, 16, env1_w2, 4, 32, 0);
    k_mlp_tc<128,16, 4,0,4><<<nbM, 256, smM128>>>(p_lat, p_lat, edge_u, edge_index, edge_attr, nullptr, E);
    k_envlin<<<(N * 16 + 255) / 256, 256>>>(envlin_ws + 256, envlin_wv + 256, N);
    k_combine<<<nbCZ, 256>>>(edge_index, E, 0);
    k_pack_l2w<<<(PACK_L2W_THREADS + 255) / 256, 256>>>(l2w1_w1, l2w1_w2);
    k_l2w_ts<<<nb256, 256, L2W_SMEM_B>>>(E);

    // ---- final: fw MLP with fused output contraction ----
    k_pack_mlp<<<packN(20, 2, 0), 256>>>(fl2w_w1, 20, fl2w_w2, 2, 16, 0);
    k_mlp_tc<160,20, 2,1,5><<<nbM, 256, smM160>>>(p_lat, p_scal, edge_u, edge_index, edge_attr, out, E);
}